// round 5
// baseline (speedup 1.0000x reference)
#include <cuda_runtime.h>
#include <cuda_bf16.h>
#include <math.h>
#include <stdint.h>

// VanillaLSTM persistent kernel (sm_103 HMMA bf16-split) + dataflow sync.
// 96 CTAs x 256 threads, all 256 steps in one kernel. Weights SMEM-resident.
// Sync: 12 per-k-chunk counters. Chunk c of h is produced by CTAs 8c..8c+7;
// consumers wait ctr[c] >= 8t before loading chunk c of step t. No global barrier.

#define ROWS 128
#define HDIM 768
#define SEQ  256
#define NCTA 96
#define NCHUNK 12
#define APITCH 144

// smem layout (bytes)
#define WS_HI 0
#define WS_LO 55296              // 12 chunks * 32 rows * 144
#define A_BASE 110592
#define ABUF 36864               // one buffer: hi(18432) + lo(18432)
#define A_HI 0
#define A_LO 18432
#define SMEM_TOTAL (A_BASE + 2 * ABUF)   // 184320

__device__ __align__(16) __nv_bfloat16 g_hhi[2][ROWS * HDIM];
__device__ __align__(16) __nv_bfloat16 g_hlo[2][ROWS * HDIM];
__device__ __align__(16) float         g_c[ROWS * HDIM];
__device__ __align__(16) __nv_bfloat16 g_Bhi[NCTA * NCHUNK * 2048];
__device__ __align__(16) __nv_bfloat16 g_Blo[NCTA * NCHUNK * 2048];
__device__ __align__(16) float2        g_wxb[NCTA * 32];
__device__ __align__(128) unsigned     g_ctr[NCHUNK][32];   // 128B-padded counters

// ---------------------------------------------------------------------------
__device__ __forceinline__ uint32_t smem_u32(const void* p) {
    uint32_t a;
    asm("{ .reg .u64 t; cvta.to.shared.u64 t, %1; cvt.u32.u64 %0, t; }" : "=r"(a) : "l"(p));
    return a;
}
__device__ __forceinline__ void cpa16(uint32_t dst, const void* src) {
    asm volatile("cp.async.cg.shared.global [%0], [%1], 16;" :: "r"(dst), "l"(src) : "memory");
}
__device__ __forceinline__ void cp_commit() {
    asm volatile("cp.async.commit_group;" ::: "memory");
}
__device__ __forceinline__ void cp_wait1() {
    asm volatile("cp.async.wait_group 1;" ::: "memory");
}
__device__ __forceinline__ void cp_wait0() {
    asm volatile("cp.async.wait_group 0;" ::: "memory");
}
__device__ __forceinline__ void ldsm4(uint32_t* r, uint32_t addr) {
    asm volatile("ldmatrix.sync.aligned.m8n8.x4.shared.b16 {%0,%1,%2,%3}, [%4];"
                 : "=r"(r[0]), "=r"(r[1]), "=r"(r[2]), "=r"(r[3]) : "r"(addr));
}
__device__ __forceinline__ void mma_bf16(float* d, const uint32_t* a, uint32_t b0, uint32_t b1) {
    asm volatile(
        "mma.sync.aligned.m16n8k16.row.col.f32.bf16.bf16.f32 "
        "{%0,%1,%2,%3}, {%4,%5,%6,%7}, {%8,%9}, {%0,%1,%2,%3};"
        : "+f"(d[0]), "+f"(d[1]), "+f"(d[2]), "+f"(d[3])
        : "r"(a[0]), "r"(a[1]), "r"(a[2]), "r"(a[3]), "r"(b0), "r"(b1));
}
__device__ __forceinline__ void ctr_wait(const unsigned* p, unsigned target) {
    unsigned v;
    do {
        asm volatile("ld.acquire.gpu.global.u32 %0, [%1];" : "=r"(v) : "l"(p) : "memory");
    } while (v < target);
}

// ---------------------------------------------------------------------------
__global__ void init_state(const float* __restrict__ h0, const float* __restrict__ c0) {
    int i = blockIdx.x * 256 + threadIdx.x;
    if (i < NCHUNK) g_ctr[i][0] = 0u;
    if (i < ROWS * HDIM) {
        float v = h0[i];
        __nv_bfloat16 hi = __float2bfloat16(v);
        g_hhi[0][i] = hi;
        g_hlo[0][i] = __float2bfloat16(v - __bfloat162float(hi));
        g_c[i] = c0[i];
    }
}

// ---------------------------------------------------------------------------
__global__ void repack(const float* __restrict__ Wi, const float* __restrict__ Wf,
                       const float* __restrict__ Wc, const float* __restrict__ Wo,
                       const float* __restrict__ bi, const float* __restrict__ bf,
                       const float* __restrict__ bc, const float* __restrict__ bo) {
    int idx = blockIdx.x * 256 + threadIdx.x;
    const int TOT = NCTA * NCHUNK * 2048;
    if (idx < TOT) {
        int kl  = idx & 63;
        int n   = (idx >> 6) & 31;
        int blk = idx >> 11;
        int kc  = blk % NCHUNK;
        int nb  = blk / NCHUNK;
        int gate = n & 3;
        int j = nb * 8 + (n >> 2);
        const float* W = (gate == 0) ? Wi : (gate == 1) ? Wf : (gate == 2) ? Wc : Wo;
        float v = W[(1 + kc * 64 + kl) * HDIM + j];
        __nv_bfloat16 hi = __float2bfloat16(v);
        g_Bhi[idx] = hi;
        g_Blo[idx] = __float2bfloat16(v - __bfloat162float(hi));
    }
    if (idx < NCTA * 32) {
        int n = idx & 31;
        int nb = idx >> 5;
        int gate = n & 3;
        int j = nb * 8 + (n >> 2);
        const float* W = (gate == 0) ? Wi : (gate == 1) ? Wf : (gate == 2) ? Wc : Wo;
        const float* B = (gate == 0) ? bi : (gate == 1) ? bf : (gate == 2) ? bc : bo;
        g_wxb[idx] = make_float2(W[j], B[j]);
    }
}

// ---------------------------------------------------------------------------
__global__ void __launch_bounds__(256, 1) lstm_persistent(const float* __restrict__ x) {
    extern __shared__ char smem[];
    const uint32_t sb = smem_u32(smem);
    const int tid = threadIdx.x;
    const int lane = tid & 31, wid = tid >> 5;
    const int nb = blockIdx.x;

    // ---------------- prologue: stage W into smem (once) ----------------
    {
        const uint4* __restrict__ sh = ((const uint4*)g_Bhi) + nb * (NCHUNK * 256);
        const uint4* __restrict__ sl = ((const uint4*)g_Blo) + nb * (NCHUNK * 256);
        for (int i = tid; i < NCHUNK * 256; i += 256) {
            int c = i >> 8, r = i & 255;
            int n = r >> 3, k8 = r & 7;
            uint32_t off = (uint32_t)(c * 4608 + n * APITCH + k8 * 16);
            *(uint4*)(smem + WS_HI + off) = sh[i];
            *(uint4*)(smem + WS_LO + off) = sl[i];
        }
    }
    __syncthreads();

    // per-thread staging slices
    const int arow0 = tid >> 3, ach = tid & 7;

    // ldmatrix lane offsets
    const int sel = lane >> 3, li = lane & 7;
    const uint32_t aoff = (uint32_t)((wid * 16 + li + (sel & 1) * 8) * APITCH + (sel >> 1) * 16);
    const uint32_t boff = (uint32_t)((li + (sel >> 1) * 8) * APITCH + (sel & 1) * 16);

    // epilogue constants
    const int my_row = wid * 16 + (lane >> 2) + (lane & 1) * 8;
    const float* __restrict__ xrow = x + (my_row >> 1) * 512 + (my_row & 1);
    const float2* __restrict__ wxbp = g_wxb + nb * 32;
    unsigned* __restrict__ my_ctr = &g_ctr[nb >> 3][0];

    for (int t = 0; t < SEQ; ++t) {
        const int par = t & 1;
        const __nv_bfloat16* __restrict__ hhi = g_hhi[par];
        const __nv_bfloat16* __restrict__ hlo = g_hlo[par];
        __nv_bfloat16* __restrict__ ohi = g_hhi[par ^ 1];
        __nv_bfloat16* __restrict__ olo = g_hlo[par ^ 1];
        const unsigned tgt = 8u * (unsigned)t;

        float d[4][4];
#pragma unroll
        for (int i = 0; i < 4; i++)
#pragma unroll
            for (int k = 0; k < 4; k++) d[i][k] = 0.f;

        auto issue = [&](int c, int b) {
            const uint32_t bufs = sb + A_BASE + b * ABUF;
#pragma unroll
            for (int u = 0; u < 4; ++u) {
                int row = arow0 + 32 * u;
                uint32_t doff = (uint32_t)(row * APITCH + ach * 16);
                const int so = row * HDIM + c * 64 + ach * 8;
                cpa16(bufs + A_HI + doff, hhi + so);
                cpa16(bufs + A_LO + doff, hlo + so);
            }
            cp_commit();
        };

        // dataflow wait for chunks 0,1 (producers: CTAs 0..15 at step t-1)
        if (t > 0 && tid == 0) {
            ctr_wait(&g_ctr[0][0], tgt);
            ctr_wait(&g_ctr[1][0], tgt);
        }
        __syncthreads();
        issue(0, 0);
        issue(1, 1);

        for (int c = 0; c < NCHUNK; ++c) {
            if (c < NCHUNK - 1) cp_wait1(); else cp_wait0();
            if (t > 0 && tid == 0 && c + 2 < NCHUNK) ctr_wait(&g_ctr[c + 2][0], tgt);
            __syncthreads();
            const uint32_t abuf = sb + A_BASE + (c & 1) * ABUF;
            const uint32_t wbase = sb + (uint32_t)(c * 4608);
#pragma unroll
            for (int ks = 0; ks < 4; ++ks) {
                uint32_t ah[4], al[4];
                ldsm4(ah, abuf + A_HI + aoff + ks * 32);
                ldsm4(al, abuf + A_LO + aoff + ks * 32);
#pragma unroll
                for (int p = 0; p < 2; ++p) {
                    uint32_t bh[4], bl[4];
                    const uint32_t bb = wbase + boff + ks * 32 + p * (16 * APITCH);
                    ldsm4(bh, bb + WS_HI);
                    ldsm4(bl, bb + WS_LO);
                    mma_bf16(d[2 * p],     ah, bh[0], bh[1]);
                    mma_bf16(d[2 * p],     ah, bl[0], bl[1]);
                    mma_bf16(d[2 * p],     al, bh[0], bh[1]);
                    mma_bf16(d[2 * p + 1], ah, bh[2], bh[3]);
                    mma_bf16(d[2 * p + 1], ah, bl[2], bl[3]);
                    mma_bf16(d[2 * p + 1], al, bh[2], bh[3]);
                }
            }
            __syncthreads();
            if (c + 2 < NCHUNK) issue(c + 2, c & 1);
        }

        // ---------------- fused LSTM epilogue ----------------
        const float xv = xrow[2 * t];
#pragma unroll
        for (int nt = 0; nt < 4; ++nt) {
            const int jl = nt * 2 + ((lane & 3) >> 1);
            float p0 = __shfl_xor_sync(0xffffffffu, d[nt][0], 1);
            float p1 = __shfl_xor_sync(0xffffffffu, d[nt][1], 1);
            float p2 = __shfl_xor_sync(0xffffffffu, d[nt][2], 1);
            float p3 = __shfl_xor_sync(0xffffffffu, d[nt][3], 1);
            float gi, gf, gc, go;
            if (!(lane & 1)) { gi = d[nt][0]; gf = d[nt][1]; gc = p0; go = p1; }
            else             { gi = p2;       gf = p3;       gc = d[nt][2]; go = d[nt][3]; }
            float2 wi = wxbp[4 * jl + 0], wf = wxbp[4 * jl + 1];
            float2 wc = wxbp[4 * jl + 2], wo = wxbp[4 * jl + 3];
            float pi = gi + xv * wi.x + wi.y;
            float pf = gf + xv * wf.x + wf.y;
            float pc = gc + xv * wc.x + wc.y;
            float po = go + xv * wo.x + wo.y;
            const int idx = my_row * HDIM + nb * 8 + jl;
            float cold = g_c[idx];
            float ig = 1.f / (1.f + expf(-pi));
            float fg = 1.f / (1.f + expf(-pf));
            float cn = fg * cold + ig * tanhf(pc);
            float hn = po * tanhf(cn);   // no sigmoid on output gate
            g_c[idx] = cn;
            __nv_bfloat16 hi = __float2bfloat16(hn);
            ohi[idx] = hi;
            olo[idx] = __float2bfloat16(hn - __bfloat162float(hi));
        }

        // publish: all h stores done (syncthreads), then release-add group counter
        if (t + 1 < SEQ) {
            __syncthreads();
            if (tid == 0) {
                asm volatile("red.release.gpu.global.add.u32 [%0], %1;"
                             :: "l"(my_ctr), "r"(1u) : "memory");
            }
        }
    }
}

// ---------------------------------------------------------------------------
__global__ void out_final(const float* __restrict__ Wout,
                          const float* __restrict__ bout,
                          float* __restrict__ out) {
    int gtid = blockIdx.x * 128 + threadIdx.x;
    int r = gtid >> 5, lane = gtid & 31;
    float s = 0.f;
    for (int k = lane; k < HDIM; k += 32) {
        float h = __bfloat162float(g_hhi[0][r * HDIM + k]) +
                  __bfloat162float(g_hlo[0][r * HDIM + k]);
        s += h * Wout[k];
    }
#pragma unroll
    for (int o = 16; o; o >>= 1) s += __shfl_xor_sync(0xffffffffu, s, o);
    if (lane == 0) out[r] = s + bout[0];
}

// ---------------------------------------------------------------------------
extern "C" void kernel_launch(void* const* d_in, const int* in_sizes, int n_in,
                              void* d_out, int out_size) {
    (void)in_sizes; (void)n_in; (void)out_size;
    const float* x    = (const float*)d_in[0];
    const float* h0   = (const float*)d_in[1];
    const float* c0   = (const float*)d_in[2];
    const float* Wi   = (const float*)d_in[3];
    const float* bi   = (const float*)d_in[4];
    const float* Wf   = (const float*)d_in[5];
    const float* bf   = (const float*)d_in[6];
    const float* Wc   = (const float*)d_in[7];
    const float* bc   = (const float*)d_in[8];
    const float* Wo   = (const float*)d_in[9];
    const float* bo   = (const float*)d_in[10];
    const float* Wout = (const float*)d_in[11];
    const float* bout = (const float*)d_in[12];
    float* out = (float*)d_out;

    static int configured = 0;
    if (!configured) {
        cudaFuncSetAttribute(lstm_persistent,
                             cudaFuncAttributeMaxDynamicSharedMemorySize, SMEM_TOTAL);
        configured = 1;
    }

    init_state<<<(ROWS * HDIM + 255) / 256, 256>>>(h0, c0);
    repack<<<(NCTA * NCHUNK * 2048 + 255) / 256, 256>>>(Wi, Wf, Wc, Wo, bi, bf, bc, bo);
    lstm_persistent<<<NCTA, 256, SMEM_TOTAL>>>(x);
    out_final<<<32, 128>>>(Wout, bout, out);
}

// round 6
// speedup vs baseline: 1.3585x; 1.3585x over previous
#include <cuda_runtime.h>
#include <cuda_bf16.h>
#include <math.h>
#include <stdint.h>

// VanillaLSTM persistent kernel (sm_103 HMMA bf16-split), warp-autonomous.
// 96 CTAs x 256 threads. Weights SMEM-resident. No __syncthreads in step loop:
// warp w touches only h rows [16w,16w+16); sync via per-(group,warp) counters
// with one batched 12-lane acquire poll per warp per step. Cell state in regs.

#define ROWS 128
#define HDIM 768
#define SEQ  256
#define NCTA 96
#define NCHUNK 12
#define APITCH 144

// smem layout (bytes)
#define WS_HI 0
#define WS_LO 55296              // 12 chunks * 32 rows * 144
#define A_BASE 110592            // 8 warps * 2 bufs * 4608 (hi 2304 + lo 2304)
#define SMEM_TOTAL (A_BASE + 8 * 2 * 4608)   // 184320

__device__ __align__(16) __nv_bfloat16 g_hhi[2][ROWS * HDIM];
__device__ __align__(16) __nv_bfloat16 g_hlo[2][ROWS * HDIM];
__device__ __align__(16) float         g_c[ROWS * HDIM];
__device__ __align__(16) __nv_bfloat16 g_Bhi[NCTA * NCHUNK * 2048];
__device__ __align__(16) __nv_bfloat16 g_Blo[NCTA * NCHUNK * 2048];
__device__ __align__(16) float2        g_wxb[NCTA * 32];
__device__ __align__(128) unsigned     g_ctr[NCHUNK * 8][32];  // (group, warp), 128B apart

// ---------------------------------------------------------------------------
__device__ __forceinline__ uint32_t smem_u32(const void* p) {
    uint32_t a;
    asm("{ .reg .u64 t; cvta.to.shared.u64 t, %1; cvt.u32.u64 %0, t; }" : "=r"(a) : "l"(p));
    return a;
}
__device__ __forceinline__ void cpa16(uint32_t dst, const void* src) {
    asm volatile("cp.async.cg.shared.global [%0], [%1], 16;" :: "r"(dst), "l"(src) : "memory");
}
__device__ __forceinline__ void cp_commit() {
    asm volatile("cp.async.commit_group;" ::: "memory");
}
__device__ __forceinline__ void cp_wait1() {
    asm volatile("cp.async.wait_group 1;" ::: "memory");
}
__device__ __forceinline__ void cp_wait0() {
    asm volatile("cp.async.wait_group 0;" ::: "memory");
}
__device__ __forceinline__ void ldsm4(uint32_t* r, uint32_t addr) {
    asm volatile("ldmatrix.sync.aligned.m8n8.x4.shared.b16 {%0,%1,%2,%3}, [%4];"
                 : "=r"(r[0]), "=r"(r[1]), "=r"(r[2]), "=r"(r[3]) : "r"(addr));
}
__device__ __forceinline__ void mma_bf16(float* d, const uint32_t* a, uint32_t b0, uint32_t b1) {
    asm volatile(
        "mma.sync.aligned.m16n8k16.row.col.f32.bf16.bf16.f32 "
        "{%0,%1,%2,%3}, {%4,%5,%6,%7}, {%8,%9}, {%0,%1,%2,%3};"
        : "+f"(d[0]), "+f"(d[1]), "+f"(d[2]), "+f"(d[3])
        : "r"(a[0]), "r"(a[1]), "r"(a[2]), "r"(a[3]), "r"(b0), "r"(b1));
}

// ---------------------------------------------------------------------------
__global__ void init_state(const float* __restrict__ h0, const float* __restrict__ c0) {
    int i = blockIdx.x * 256 + threadIdx.x;
    if (i < NCHUNK * 8) g_ctr[i][0] = 0u;
    if (i < ROWS * HDIM) {
        float v = h0[i];
        __nv_bfloat16 hi = __float2bfloat16(v);
        g_hhi[0][i] = hi;
        g_hlo[0][i] = __float2bfloat16(v - __bfloat162float(hi));
        g_c[i] = c0[i];
    }
}

// ---------------------------------------------------------------------------
__global__ void repack(const float* __restrict__ Wi, const float* __restrict__ Wf,
                       const float* __restrict__ Wc, const float* __restrict__ Wo,
                       const float* __restrict__ bi, const float* __restrict__ bf,
                       const float* __restrict__ bc, const float* __restrict__ bo) {
    int idx = blockIdx.x * 256 + threadIdx.x;
    const int TOT = NCTA * NCHUNK * 2048;
    if (idx < TOT) {
        int kl  = idx & 63;
        int n   = (idx >> 6) & 31;
        int blk = idx >> 11;
        int kc  = blk % NCHUNK;
        int nb  = blk / NCHUNK;
        int gate = n & 3;
        int j = nb * 8 + (n >> 2);
        const float* W = (gate == 0) ? Wi : (gate == 1) ? Wf : (gate == 2) ? Wc : Wo;
        float v = W[(1 + kc * 64 + kl) * HDIM + j];
        __nv_bfloat16 hi = __float2bfloat16(v);
        g_Bhi[idx] = hi;
        g_Blo[idx] = __float2bfloat16(v - __bfloat162float(hi));
    }
    if (idx < NCTA * 32) {
        int n = idx & 31;
        int nb = idx >> 5;
        int gate = n & 3;
        int j = nb * 8 + (n >> 2);
        const float* W = (gate == 0) ? Wi : (gate == 1) ? Wf : (gate == 2) ? Wc : Wo;
        const float* B = (gate == 0) ? bi : (gate == 1) ? bf : (gate == 2) ? bc : bo;
        g_wxb[idx] = make_float2(W[j], B[j]);
    }
}

// ---------------------------------------------------------------------------
__global__ void __launch_bounds__(256, 1) lstm_persistent(const float* __restrict__ x) {
    extern __shared__ char smem[];
    const uint32_t sb = smem_u32(smem);
    const int tid = threadIdx.x;
    const int lane = tid & 31, wid = tid >> 5;
    const int nb = blockIdx.x;

    // ---------------- prologue: stage W into smem (once) ----------------
    {
        const uint4* __restrict__ sh = ((const uint4*)g_Bhi) + nb * (NCHUNK * 256);
        const uint4* __restrict__ sl = ((const uint4*)g_Blo) + nb * (NCHUNK * 256);
        for (int i = tid; i < NCHUNK * 256; i += 256) {
            int c = i >> 8, r = i & 255;
            int n = r >> 3, k8 = r & 7;
            uint32_t off = (uint32_t)(c * 4608 + n * APITCH + k8 * 16);
            *(uint4*)(smem + WS_HI + off) = sh[i];
            *(uint4*)(smem + WS_LO + off) = sl[i];
        }
    }
    __syncthreads();

    const int w16 = wid * 16;
    const uint32_t abase = sb + A_BASE + wid * 9216;    // 2 bufs x 4608

    // ldmatrix lane offsets
    const int sel = lane >> 3, li = lane & 7;
    const uint32_t aoff = (uint32_t)((li + (sel & 1) * 8) * APITCH + (sel >> 1) * 16);
    const uint32_t boff = (uint32_t)((li + (sel >> 1) * 8) * APITCH + (sel & 1) * 16);

    // epilogue constants
    const int my_row = w16 + (lane >> 2) + (lane & 1) * 8;
    const float* __restrict__ xrow = x + (my_row >> 1) * 512 + (my_row & 1);

    // registers: wxb, cell state
    float2 wxr[8];
    float  creg[4];
    {
        const float2* __restrict__ wxbp = g_wxb + nb * 32;
#pragma unroll
        for (int q = 0; q < 8; ++q) wxr[q] = wxbp[((q >> 1) * 2 + ((lane & 3) >> 1)) * 4 + (q & 1) * 2 + 0 + 0];
        // simpler: reload exactly per use below; instead load the 4 jl groups:
    }
    // load the 16 wxb floats we actually use: jl(nt) = nt*2 + ((lane&3)>>1)
    float2 wxi[4], wxf[4], wxc[4], wxo[4];
    {
        const float2* __restrict__ wxbp = g_wxb + nb * 32;
#pragma unroll
        for (int nt = 0; nt < 4; ++nt) {
            int jl = nt * 2 + ((lane & 3) >> 1);
            wxi[nt] = wxbp[4 * jl + 0];
            wxf[nt] = wxbp[4 * jl + 1];
            wxc[nt] = wxbp[4 * jl + 2];
            wxo[nt] = wxbp[4 * jl + 3];
        }
#pragma unroll
        for (int nt = 0; nt < 4; ++nt) {
            int jl = nt * 2 + ((lane & 3) >> 1);
            creg[nt] = g_c[my_row * HDIM + nb * 8 + jl];
        }
    }

    // sync pointers
    const unsigned* __restrict__ pollp =
        (lane < NCHUNK) ? &g_ctr[lane * 8 + wid][0] : &g_ctr[0][0];
    unsigned* __restrict__ relp = &g_ctr[(nb >> 3) * 8 + wid][0];

    for (int t = 0; t < SEQ; ++t) {
        const int par = t & 1;
        const __nv_bfloat16* __restrict__ hhi = g_hhi[par];
        const __nv_bfloat16* __restrict__ hlo = g_hlo[par];
        __nv_bfloat16* __restrict__ ohi = g_hhi[par ^ 1];
        __nv_bfloat16* __restrict__ olo = g_hlo[par ^ 1];

        // ---- batched dataflow wait: lanes 0..11 poll all 12 group counters ----
        if (t > 0) {
            const unsigned tgt = 8u * (unsigned)t;
            const bool mine = (lane < NCHUNK);
            for (;;) {
                unsigned v = tgt;
                if (mine) {
                    asm volatile("ld.acquire.gpu.global.u32 %0, [%1];"
                                 : "=r"(v) : "l"(pollp) : "memory");
                }
                if (__all_sync(0xffffffffu, v >= tgt)) break;
            }
        }
        __syncwarp();

        float d[4][4];
#pragma unroll
        for (int i = 0; i < 4; i++)
#pragma unroll
            for (int k = 0; k < 4; k++) d[i][k] = 0.f;

        // per-warp A staging: 16 rows x 64 k, hi+lo
        auto issue = [&](int c, int b) {
            const uint32_t bufs = abase + b * 4608;
#pragma unroll
            for (int i = 0; i < 4; ++i) {
                int o = lane * 4 + i;            // 0..127
                int row = o >> 3, seg = o & 7;
                uint32_t dst = bufs + (uint32_t)(row * APITCH + seg * 16);
                const int so = (w16 + row) * HDIM + c * 64 + seg * 8;
                cpa16(dst, hhi + so);
                cpa16(dst + 2304, hlo + so);
            }
            cp_commit();
        };

        issue(0, 0);
        issue(1, 1);

        for (int c = 0; c < NCHUNK; ++c) {
            if (c < NCHUNK - 1) cp_wait1(); else cp_wait0();
            __syncwarp();
            const uint32_t abuf = abase + (c & 1) * 4608;
            const uint32_t wbase = sb + (uint32_t)(c * 4608);
#pragma unroll
            for (int ks = 0; ks < 4; ++ks) {
                uint32_t ah[4], al[4];
                ldsm4(ah, abuf + aoff + ks * 32);
                ldsm4(al, abuf + 2304 + aoff + ks * 32);
#pragma unroll
                for (int p = 0; p < 2; ++p) {
                    uint32_t bh[4], bl[4];
                    const uint32_t bb = wbase + boff + ks * 32 + p * (16 * APITCH);
                    ldsm4(bh, bb + WS_HI);
                    ldsm4(bl, bb + WS_LO);
                    mma_bf16(d[2 * p],     ah, bh[0], bh[1]);
                    mma_bf16(d[2 * p],     ah, bl[0], bl[1]);
                    mma_bf16(d[2 * p],     al, bh[0], bh[1]);
                    mma_bf16(d[2 * p + 1], ah, bh[2], bh[3]);
                    mma_bf16(d[2 * p + 1], ah, bl[2], bl[3]);
                    mma_bf16(d[2 * p + 1], al, bh[2], bh[3]);
                }
            }
            __syncwarp();
            if (c + 2 < NCHUNK) issue(c + 2, c & 1);
        }

        // ---------------- fused LSTM epilogue (warp-local rows) ----------------
        const float xv = xrow[2 * t];
#pragma unroll
        for (int nt = 0; nt < 4; ++nt) {
            const int jl = nt * 2 + ((lane & 3) >> 1);
            float p0 = __shfl_xor_sync(0xffffffffu, d[nt][0], 1);
            float p1 = __shfl_xor_sync(0xffffffffu, d[nt][1], 1);
            float p2 = __shfl_xor_sync(0xffffffffu, d[nt][2], 1);
            float p3 = __shfl_xor_sync(0xffffffffu, d[nt][3], 1);
            float gi, gf, gc, go;
            if (!(lane & 1)) { gi = d[nt][0]; gf = d[nt][1]; gc = p0; go = p1; }
            else             { gi = p2;       gf = p3;       gc = d[nt][2]; go = d[nt][3]; }
            float pi = gi + xv * wxi[nt].x + wxi[nt].y;
            float pf = gf + xv * wxf[nt].x + wxf[nt].y;
            float pc = gc + xv * wxc[nt].x + wxc[nt].y;
            float po = go + xv * wxo[nt].x + wxo[nt].y;
            float ig = __fdividef(1.f, 1.f + __expf(-pi));
            float fg = __fdividef(1.f, 1.f + __expf(-pf));
            float thc = 1.f - __fdividef(2.f, 1.f + __expf(2.f * pc));
            float cn = fg * creg[nt] + ig * thc;
            float thn = 1.f - __fdividef(2.f, 1.f + __expf(2.f * cn));
            float hn = po * thn;            // no sigmoid on output gate
            creg[nt] = cn;
            const int idx = my_row * HDIM + nb * 8 + jl;
            __nv_bfloat16 hi = __float2bfloat16(hn);
            ohi[idx] = hi;
            olo[idx] = __float2bfloat16(hn - __bfloat162float(hi));
        }

        // publish this warp's rows (release after all lanes' stores)
        if (t + 1 < SEQ) {
            __syncwarp();
            if (lane == 0) {
                asm volatile("membar.gl;" ::: "memory");
                asm volatile("red.release.gpu.global.add.u32 [%0], %1;"
                             :: "l"(relp), "r"(1u) : "memory");
            }
        }
    }
}

// ---------------------------------------------------------------------------
__global__ void out_final(const float* __restrict__ Wout,
                          const float* __restrict__ bout,
                          float* __restrict__ out) {
    int gtid = blockIdx.x * 128 + threadIdx.x;
    int r = gtid >> 5, lane = gtid & 31;
    float s = 0.f;
    for (int k = lane; k < HDIM; k += 32) {
        float h = __bfloat162float(g_hhi[0][r * HDIM + k]) +
                  __bfloat162float(g_hlo[0][r * HDIM + k]);
        s += h * Wout[k];
    }
#pragma unroll
    for (int o = 16; o; o >>= 1) s += __shfl_xor_sync(0xffffffffu, s, o);
    if (lane == 0) out[r] = s + bout[0];
}

// ---------------------------------------------------------------------------
extern "C" void kernel_launch(void* const* d_in, const int* in_sizes, int n_in,
                              void* d_out, int out_size) {
    (void)in_sizes; (void)n_in; (void)out_size;
    const float* x    = (const float*)d_in[0];
    const float* h0   = (const float*)d_in[1];
    const float* c0   = (const float*)d_in[2];
    const float* Wi   = (const float*)d_in[3];
    const float* bi   = (const float*)d_in[4];
    const float* Wf   = (const float*)d_in[5];
    const float* bf   = (const float*)d_in[6];
    const float* Wc   = (const float*)d_in[7];
    const float* bc   = (const float*)d_in[8];
    const float* Wo   = (const float*)d_in[9];
    const float* bo   = (const float*)d_in[10];
    const float* Wout = (const float*)d_in[11];
    const float* bout = (const float*)d_in[12];
    float* out = (float*)d_out;

    static int configured = 0;
    if (!configured) {
        cudaFuncSetAttribute(lstm_persistent,
                             cudaFuncAttributeMaxDynamicSharedMemorySize, SMEM_TOTAL);
        configured = 1;
    }

    init_state<<<(ROWS * HDIM + 255) / 256, 256>>>(h0, c0);
    repack<<<(NCTA * NCHUNK * 2048 + 255) / 256, 256>>>(Wi, Wf, Wc, Wo, bi, bf, bc, bo);
    lstm_persistent<<<NCTA, 256, SMEM_TOTAL>>>(x);
    out_final<<<32, 128>>>(Wout, bout, out);
}